// round 2
// baseline (speedup 1.0000x reference)
#include <cuda_runtime.h>
#include <math.h>

// ---------------- problem constants ----------------
#define EE    4
#define NTOK  8192
#define DIN   1024
#define DD    512
#define LL    64
#define SS    128          // NTOK / LL
#define MMEM  2
#define KMEM  32
#define HH    8
#define DHH   64
#define FFN   2048
#define HIDN  1024
#define SD    22.62741699796952f   // sqrt(512)

// ---------------- scratch (device globals; allocation-free) ----------------
__device__ float g_H  [EE * NTOK * HIDN];   // aligner hidden  (128 MiB)
__device__ float g_F  [EE * NTOK * DD];     // aligner out -> f (64 MiB)
__device__ float g_U  [EE * LL * DD];
__device__ float g_CS [EE * LL * DD];
__device__ float g_TOK[EE * LL * DD];
__device__ float g_TN [EE * LL * DD];
__device__ float g_XIN[EE * LL * DD];
__device__ float g_QKV[EE * LL * 3 * DD];
__device__ float g_AO [EE * LL * DD];
__device__ float g_S1 [EE * LL * DD];
__device__ float g_X1 [EE * LL * DD];
__device__ float g_FFH[EE * LL * FFN];
__device__ float g_S2 [EE * LL * DD];
__device__ float g_EO [EE * LL * DD];
__device__ float g_RC [EE * LL * MMEM * DD];
__device__ float g_EOUT[EE * LL * DD];

// ---------------- reduction helpers ----------------
__device__ __forceinline__ float warpSum(float v) {
#pragma unroll
    for (int o = 16; o; o >>= 1) v += __shfl_xor_sync(0xffffffffu, v, o);
    return v;
}
__device__ __forceinline__ float warpMax(float v) {
#pragma unroll
    for (int o = 16; o; o >>= 1) v = fmaxf(v, __shfl_xor_sync(0xffffffffu, v, o));
    return v;
}
__device__ __forceinline__ float blockSum(float v, float* sw, int tid, int nw) {
    int lane = tid & 31, w = tid >> 5;
    v = warpSum(v);
    if (lane == 0) sw[w] = v;
    __syncthreads();
    float t = 0.f;
    for (int i = 0; i < nw; i++) t += sw[i];
    __syncthreads();
    return t;
}
__device__ __forceinline__ float blockMax(float v, float* sw, int tid, int nw) {
    int lane = tid & 31, w = tid >> 5;
    v = warpMax(v);
    if (lane == 0) sw[w] = v;
    __syncthreads();
    float t = -1e30f;
    for (int i = 0; i < nw; i++) t = fmaxf(t, sw[i]);
    __syncthreads();
    return t;
}
__device__ __forceinline__ float clip5(float x) { return fminf(fmaxf(x, -5.f), 5.f); }

// ---------------- big SGEMM: 128x128 tile, BK=16, 256 thr, 8x8/thread ----------------
__global__ __launch_bounds__(256, 2)
void sgemm128(const float* __restrict__ A, const float* __restrict__ B,
              const float* __restrict__ bias, float* __restrict__ C,
              int Ncols, int Kdim, int relu,
              long aStr, long bStr, long biasStr, long cStr)
{
    const int e = blockIdx.z;
    A    += (long)e * aStr;
    B    += (long)e * bStr;
    bias += (long)e * biasStr;
    C    += (long)e * cStr;
    const int bx = blockIdx.x, by = blockIdx.y;

    __shared__ float As[16][128];
    __shared__ float Bs[16][128];

    const int tid = threadIdx.x;
    const int tx = tid & 15, ty = tid >> 4;

    float acc[8][8] = {};

    const int a_r = tid >> 2,  a_c = (tid & 3) << 2;    // A tile 128x16
    const int b_r = tid >> 5,  b_c = (tid & 31) << 2;   // B tile 16x128

    const float* Ab = A + (long)(by * 128 + a_r) * Kdim + a_c;
    const float* Bb = B + (long)b_r * Ncols + bx * 128 + b_c;

    for (int kt = 0; kt < Kdim; kt += 16) {
        float4 va0 = *(const float4*)(Ab + kt);
        float4 va1 = *(const float4*)(Ab + 64l * Kdim + kt);
        float4 vb0 = *(const float4*)(Bb + (long)kt * Ncols);
        float4 vb1 = *(const float4*)(Bb + (long)(kt + 8) * Ncols);

        As[a_c + 0][a_r] = va0.x; As[a_c + 1][a_r] = va0.y;
        As[a_c + 2][a_r] = va0.z; As[a_c + 3][a_r] = va0.w;
        As[a_c + 0][a_r + 64] = va1.x; As[a_c + 1][a_r + 64] = va1.y;
        As[a_c + 2][a_r + 64] = va1.z; As[a_c + 3][a_r + 64] = va1.w;
        *(float4*)&Bs[b_r][b_c]     = vb0;
        *(float4*)&Bs[b_r + 8][b_c] = vb1;
        __syncthreads();

#pragma unroll
        for (int kk = 0; kk < 16; kk++) {
            float4 a0 = *(const float4*)&As[kk][ty * 4];
            float4 a1 = *(const float4*)&As[kk][ty * 4 + 64];
            float4 b0 = *(const float4*)&Bs[kk][tx * 4];
            float4 b1 = *(const float4*)&Bs[kk][tx * 4 + 64];
            float ar[8] = {a0.x, a0.y, a0.z, a0.w, a1.x, a1.y, a1.z, a1.w};
            float br[8] = {b0.x, b0.y, b0.z, b0.w, b1.x, b1.y, b1.z, b1.w};
#pragma unroll
            for (int i = 0; i < 8; i++)
#pragma unroll
                for (int j = 0; j < 8; j++)
                    acc[i][j] += ar[i] * br[j];
        }
        __syncthreads();
    }

#pragma unroll
    for (int i = 0; i < 8; i++) {
        int row = by * 128 + ty * 4 + ((i < 4) ? i : 60 + i);
#pragma unroll
        for (int jh = 0; jh < 2; jh++) {
            int col = bx * 128 + tx * 4 + jh * 64;
            float4 v;
            v.x = acc[i][jh * 4 + 0] + bias[col + 0];
            v.y = acc[i][jh * 4 + 1] + bias[col + 1];
            v.z = acc[i][jh * 4 + 2] + bias[col + 2];
            v.w = acc[i][jh * 4 + 3] + bias[col + 3];
            if (relu) {
                v.x = fmaxf(v.x, 0.f); v.y = fmaxf(v.y, 0.f);
                v.z = fmaxf(v.z, 0.f); v.w = fmaxf(v.w, 0.f);
            }
            *(float4*)(C + (long)row * Ncols + col) = v;
        }
    }
}

// ---------------- small SGEMM: 64 rows, 64-col tiles, BK=16, 4x4/thread ----------------
__global__ __launch_bounds__(256)
void sgemm64(const float* __restrict__ A, const float* __restrict__ B,
             const float* __restrict__ bias, const float* __restrict__ addend,
             float* __restrict__ C,
             int Ncols, int Kdim, int relu,
             long aStr, long bStr, long biasStr, long addStr, long cStr)
{
    const int e = blockIdx.z;
    A += (long)e * aStr;
    B += (long)e * bStr;
    C += (long)e * cStr;
    const float* biasE = bias ? bias + (long)e * biasStr : nullptr;
    const float* addE  = addend ? addend + (long)e * addStr : nullptr;
    const int bx = blockIdx.x;

    __shared__ float As[16][64];
    __shared__ float Bs[16][64];

    const int tid = threadIdx.x;
    const int tx = tid & 15, ty = tid >> 4;

    float acc[4][4] = {};

    const int a_r = tid >> 2,  a_c = (tid & 3) << 2;   // 64x16
    const int b_r = tid >> 4,  b_c = (tid & 15) << 2;  // 16x64

    const float* Ab = A + (long)a_r * Kdim + a_c;
    const float* Bb = B + (long)b_r * Ncols + bx * 64 + b_c;

    for (int kt = 0; kt < Kdim; kt += 16) {
        float4 va = *(const float4*)(Ab + kt);
        float4 vb = *(const float4*)(Bb + (long)kt * Ncols);
        As[a_c + 0][a_r] = va.x; As[a_c + 1][a_r] = va.y;
        As[a_c + 2][a_r] = va.z; As[a_c + 3][a_r] = va.w;
        *(float4*)&Bs[b_r][b_c] = vb;
        __syncthreads();
#pragma unroll
        for (int kk = 0; kk < 16; kk++) {
            float4 a = *(const float4*)&As[kk][ty * 4];
            float4 b = *(const float4*)&Bs[kk][tx * 4];
            float ar[4] = {a.x, a.y, a.z, a.w};
            float br[4] = {b.x, b.y, b.z, b.w};
#pragma unroll
            for (int i = 0; i < 4; i++)
#pragma unroll
                for (int j = 0; j < 4; j++)
                    acc[i][j] += ar[i] * br[j];
        }
        __syncthreads();
    }

#pragma unroll
    for (int i = 0; i < 4; i++) {
        int row = ty * 4 + i;
        int col = bx * 64 + tx * 4;
        float4 v;
        v.x = acc[i][0]; v.y = acc[i][1]; v.z = acc[i][2]; v.w = acc[i][3];
        if (biasE) {
            v.x += biasE[col + 0]; v.y += biasE[col + 1];
            v.z += biasE[col + 2]; v.w += biasE[col + 3];
        }
        if (addE) {
            float4 a = *(const float4*)(addE + (long)row * Ncols + col);
            v.x += a.x; v.y += a.y; v.z += a.z; v.w += a.w;
        }
        if (relu) {
            v.x = fmaxf(v.x, 0.f); v.y = fmaxf(v.y, 0.f);
            v.z = fmaxf(v.z, 0.f); v.w = fmaxf(v.w, 0.f);
        }
        *(float4*)(C + (long)row * Ncols + col) = v;
    }
}

// ---------------- aligner double-LN (in place on g_F): f = LN(LN(y)*g + bt) ----------------
__global__ __launch_bounds__(128)
void aligner_ln(const float* __restrict__ g, const float* __restrict__ bt)
{
    __shared__ float sw[4];
    const int row = blockIdx.x;          // E*NTOK rows
    const int e = row >> 13;             // / 8192
    const int tid = threadIdx.x;
    float* rp = g_F + (long)row * DD;

    float v[4]; float s = 0.f, q = 0.f;
#pragma unroll
    for (int i = 0; i < 4; i++) {
        v[i] = rp[tid + i * 128];
        s += v[i]; q += v[i] * v[i];
    }
    s = blockSum(s, sw, tid, 4);
    q = blockSum(q, sw, tid, 4);
    float mu = s * (1.f / DD);
    float rstd = rsqrtf(q * (1.f / DD) - mu * mu + 1e-5f);

    float s2 = 0.f, q2 = 0.f;
#pragma unroll
    for (int i = 0; i < 4; i++) {
        int d = tid + i * 128;
        v[i] = (v[i] - mu) * rstd * g[e * DD + d] + bt[e * DD + d];
        s2 += v[i]; q2 += v[i] * v[i];
    }
    s2 = blockSum(s2, sw, tid, 4);
    q2 = blockSum(q2, sw, tid, 4);
    mu = s2 * (1.f / DD);
    rstd = rsqrtf(q2 * (1.f / DD) - mu * mu + 1e-5f);
#pragma unroll
    for (int i = 0; i < 4; i++)
        rp[tid + i * 128] = (v[i] - mu) * rstd;
}

// ---------------- generic row LN (rows = E*LL) ----------------
__global__ __launch_bounds__(128)
void ln_rows(const float* __restrict__ in, float* __restrict__ out,
             const float* __restrict__ gamma, const float* __restrict__ beta)
{
    __shared__ float sw[4];
    const int row = blockIdx.x;
    const int e = row >> 6;
    const int tid = threadIdx.x;
    const float* rp = in + (long)row * DD;

    float v[4]; float s = 0.f, q = 0.f;
#pragma unroll
    for (int i = 0; i < 4; i++) {
        v[i] = rp[tid + i * 128];
        s += v[i]; q += v[i] * v[i];
    }
    s = blockSum(s, sw, tid, 4);
    q = blockSum(q, sw, tid, 4);
    float mu = s * (1.f / DD);
    float rstd = rsqrtf(q * (1.f / DD) - mu * mu + 1e-5f);
#pragma unroll
    for (int i = 0; i < 4; i++) {
        int d = tid + i * 128;
        float o = (v[i] - mu) * rstd;
        if (gamma) o = o * gamma[e * DD + d] + beta[e * DD + d];
        out[(long)row * DD + d] = o;
    }
}

// ---------------- LSTCWA stage 1: u = wk @ (z @ wq) ----------------
__global__ __launch_bounds__(256)
void qu_kernel(const float* __restrict__ z, const float* __restrict__ wq,
               const float* __restrict__ wk)
{
    const int row = blockIdx.x;   // e*64 + l
    const int e = row >> 6;
    const int tid = threadIdx.x;
    __shared__ float zr[DD];
    __shared__ float qv[DD];

    zr[tid] = z[(long)row * DD + tid];
    zr[tid + 256] = z[(long)row * DD + tid + 256];
    __syncthreads();

    const float* Wq = wq + (long)e * DD * DD;
#pragma unroll
    for (int rep = 0; rep < 2; rep++) {
        int j = tid + rep * 256;
        float a = 0.f;
        for (int i = 0; i < DD; i++) a += zr[i] * Wq[(long)i * DD + j];
        qv[j] = a;
    }
    __syncthreads();

    const float* Wk = wk + (long)e * DD * DD;
    const int lane = tid & 31, w = tid >> 5;
    for (int d = w; d < DD; d += 8) {
        const float* r = Wk + (long)d * DD;
        float p = 0.f;
        for (int t = lane; t < DD; t += 32) p += r[t] * qv[t];
        p = warpSum(p);
        if (lane == 0) g_U[(long)row * DD + d] = p;
    }
}

// ---------------- LSTCWA stage 2: seg softmax + weighted segment sum ----------------
__global__ __launch_bounds__(128)
void seg_attn()
{
    const int row = blockIdx.x;   // e*64 + l
    const int e = row >> 6, l = row & 63;
    const int tid = threadIdx.x;
    const int lane = tid & 31, w = tid >> 5;
    __shared__ float u[DD];
    __shared__ float sc[SS];
    __shared__ float sw[4];

#pragma unroll
    for (int i = 0; i < 4; i++) u[tid + i * 128] = g_U[(long)row * DD + tid + i * 128];
    __syncthreads();

    const float* F = g_F + ((long)e * NTOK + (long)l * SS) * DD;
    for (int s = w; s < SS; s += 4) {
        const float* fr = F + (long)s * DD;
        float p = 0.f;
        for (int t = lane; t < DD; t += 32) p += fr[t] * u[t];
        p = warpSum(p);
        if (lane == 0) sc[s] = clip5(p * (1.f / SD));
    }
    __syncthreads();

    float x = sc[tid];
    float mx = blockMax(x, sw, tid, 4);
    float ex = expf(x - mx);
    float sum = blockSum(ex, sw, tid, 4);
    sc[tid] = ex / sum;
    __syncthreads();

    for (int d = tid; d < DD; d += 128) {
        float a = 0.f;
        for (int s = 0; s < SS; s++) a += sc[s] * F[(long)s * DD + d];
        g_CS[(long)row * DD + d] = a;
    }
}

// ---------------- LSTCWA stage 3: zo = cs @ wv ; tokens = zo @ wo + bo ----------------
__global__ __launch_bounds__(256)
void zo_tok(const float* __restrict__ wv, const float* __restrict__ wo,
            const float* __restrict__ bo)
{
    const int row = blockIdx.x;
    const int e = row >> 6;
    const int tid = threadIdx.x;
    __shared__ float c[DD];
    __shared__ float zo[DD];

    c[tid] = g_CS[(long)row * DD + tid];
    c[tid + 256] = g_CS[(long)row * DD + tid + 256];
    __syncthreads();

    const float* Wv = wv + (long)e * DD * DD;
#pragma unroll
    for (int rep = 0; rep < 2; rep++) {
        int k = tid + rep * 256;
        float a = 0.f;
        for (int d = 0; d < DD; d++) a += c[d] * Wv[(long)d * DD + k];
        zo[k] = a;
    }
    __syncthreads();

    const float* Wo = wo + (long)e * DD * DD;
#pragma unroll
    for (int rep = 0; rep < 2; rep++) {
        int dd = tid + rep * 256;
        float a = bo[e * DD + dd];
        for (int k = 0; k < DD; k++) a += zo[k] * Wo[(long)k * DD + dd];
        g_TOK[(long)row * DD + dd] = a;
    }
}

// ---------------- cross-backbone context attention ----------------
__global__ __launch_bounds__(128)
void cross_ctx()
{
    const int row = blockIdx.x;
    const int e = row >> 6;
    const int ec = (e == 0) ? 1 : 0;
    const int tid = threadIdx.x;
    const int lane = tid & 31, w = tid >> 5;
    __shared__ float tr[DD];
    __shared__ float sc[LL];
    __shared__ float sw[4];

#pragma unroll
    for (int i = 0; i < 4; i++) tr[tid + i * 128] = g_TN[(long)row * DD + tid + i * 128];
    __syncthreads();

    const float* C = g_TN + (long)ec * LL * DD;
    for (int m = w; m < LL; m += 4) {
        const float* cr = C + (long)m * DD;
        float p = 0.f;
        for (int t = lane; t < DD; t += 32) p += tr[t] * cr[t];
        p = warpSum(p);
        if (lane == 0) sc[m] = clip5(p * (1.f / SD));
    }
    __syncthreads();

    float x = (tid < LL) ? sc[tid] : -1e30f;
    float mx = blockMax(x, sw, tid, 4);
    float ex = (tid < LL) ? expf(x - mx) : 0.f;
    float sum = blockSum(ex, sw, tid, 4);
    if (tid < LL) sc[tid] = ex / sum;
    __syncthreads();

    for (int d = tid; d < DD; d += 128) {
        float a = tr[d];
        for (int m = 0; m < LL; m++) a += sc[m] * C[(long)m * DD + d];
        g_XIN[(long)row * DD + d] = a;
    }
}

// ---------------- MHA (per expert, per head); scores kept in registers ----------------
// smem: ks + vs = 32 KiB (static-smem limit safe)
__global__ __launch_bounds__(64)
void mha()
{
    const int e = blockIdx.x >> 3;
    const int h = blockIdx.x & 7;
    const int tid = threadIdx.x;     // = query index l
    __shared__ float ks[64 * 64];
    __shared__ float vs[64 * 64];

    const float* Q = g_QKV + (long)e * LL * 1536;
    for (int idx = tid; idx < 4096; idx += 64) {
        int m = idx >> 6, d = idx & 63;
        ks[idx] = Q[(long)m * 1536 + 512 + h * 64 + d];
        vs[idx] = Q[(long)m * 1536 + 1024 + h * 64 + d];
    }
    float qv[64];
#pragma unroll
    for (int i = 0; i < 64; i++) qv[i] = Q[(long)tid * 1536 + h * 64 + i];
    __syncthreads();

    // scores in registers (fully unrolled so srow stays register-resident)
    float srow[64];
    float mx = -1e30f;
#pragma unroll
    for (int m = 0; m < 64; m++) {
        float s = 0.f;
#pragma unroll
        for (int i = 0; i < 64; i++) s += qv[i] * ks[m * 64 + i];
        s *= 0.125f;
        srow[m] = s;
        mx = fmaxf(mx, s);
    }
    float sum = 0.f;
#pragma unroll
    for (int m = 0; m < 64; m++) {
        float p = expf(srow[m] - mx);
        srow[m] = p;
        sum += p;
    }
    float inv = 1.f / sum;
#pragma unroll
    for (int m = 0; m < 64; m++) srow[m] *= inv;

    for (int d = 0; d < 64; d++) {
        float a = 0.f;
#pragma unroll
        for (int m = 0; m < 64; m++) a += srow[m] * vs[m * 64 + d];
        g_AO[((long)e * LL + tid) * DD + h * 64 + d] = a;
    }
}

// ---------------- hierarchical memory retrieval ----------------
__global__ __launch_bounds__(128)
void mem_retr(const float* __restrict__ mem)
{
    const int row = blockIdx.x;
    const int tid = threadIdx.x;
    const int lane = tid & 31, w = tid >> 5;
    __shared__ float er[DD];
    __shared__ float sa[MMEM * KMEM];

#pragma unroll
    for (int i = 0; i < 4; i++) er[tid + i * 128] = g_EO[(long)row * DD + tid + i * 128];
    __syncthreads();

    for (int p = w; p < MMEM * KMEM; p += 4) {
        const float* mr = mem + (long)p * DD;
        float s = 0.f;
        for (int t = lane; t < DD; t += 32) s += er[t] * mr[t];
        s = warpSum(s);
        if (lane == 0) sa[p] = clip5(s * (1.f / SD));
    }
    __syncthreads();

    if (tid < MMEM) {
        float mx = -1e30f;
        for (int k = 0; k < KMEM; k++) mx = fmaxf(mx, sa[tid * KMEM + k]);
        float sum = 0.f;
        for (int k = 0; k < KMEM; k++) {
            float pz = expf(sa[tid * KMEM + k] - mx);
            sa[tid * KMEM + k] = pz;
            sum += pz;
        }
        float inv = 1.f / sum;
        for (int k = 0; k < KMEM; k++) sa[tid * KMEM + k] *= inv;
    }
    __syncthreads();

    for (int d = tid; d < DD; d += 128) {
        float r0 = 0.f, r1 = 0.f;
        for (int k = 0; k < KMEM; k++) {
            r0 += sa[k] * mem[(long)k * DD + d];
            r1 += sa[KMEM + k] * mem[(long)(KMEM + k) * DD + d];
        }
        g_RC[(long)row * (MMEM * DD) + d] = r0;
        g_RC[(long)row * (MMEM * DD) + DD + d] = r1;
    }
}

// ---------------- global gating + fusion ----------------
__global__ __launch_bounds__(512)
void fuse(const float* __restrict__ gate, float* __restrict__ out, int write_gw)
{
    __shared__ float sw[16];
    __shared__ float logit[EE];
    __shared__ float gws[EE];
    const int tid = threadIdx.x;

    for (int e = 0; e < EE; e++) {
        float p = 0.f;
        for (int idx = tid; idx < LL * DD; idx += 512)
            p += g_EOUT[(long)e * LL * DD + idx] * gate[idx & (DD - 1)];
        p = blockSum(p, sw, tid, 16);
        if (tid == 0) logit[e] = p * (1.f / LL);
        __syncthreads();
    }
    if (tid == 0) {
        float mx = -1e30f;
        float c[EE];
        for (int e = 0; e < EE; e++) { c[e] = clip5(logit[e]); mx = fmaxf(mx, c[e]); }
        float sum = 0.f;
        for (int e = 0; e < EE; e++) { c[e] = expf(c[e] - mx); sum += c[e]; }
        for (int e = 0; e < EE; e++) {
            gws[e] = c[e] / sum;
            if (write_gw) out[LL * DD + e] = gws[e];
        }
    }
    __syncthreads();
    for (int idx = tid; idx < LL * DD; idx += 512) {
        float a = 0.f;
        for (int e = 0; e < EE; e++) a += gws[e] * g_EOUT[(long)e * LL * DD + idx];
        out[idx] = a;
    }
}

// ---------------- host launcher ----------------
extern "C" void kernel_launch(void* const* d_in, const int* in_sizes, int n_in,
                              void* d_out, int out_size)
{
    (void)in_sizes; (void)n_in;
    const float* x          = (const float*)d_in[0];
    const float* al_w1      = (const float*)d_in[1];
    const float* al_b1      = (const float*)d_in[2];
    const float* al_w2      = (const float*)d_in[3];
    const float* al_b2      = (const float*)d_in[4];
    const float* al_g       = (const float*)d_in[5];
    const float* al_bt      = (const float*)d_in[6];
    const float* z          = (const float*)d_in[7];
    const float* wq         = (const float*)d_in[8];
    const float* wk         = (const float*)d_in[9];
    const float* wv         = (const float*)d_in[10];
    const float* wo         = (const float*)d_in[11];
    const float* bo         = (const float*)d_in[12];
    const float* attn_in_w  = (const float*)d_in[13];
    const float* attn_in_b  = (const float*)d_in[14];
    const float* attn_out_w = (const float*)d_in[15];
    const float* attn_out_b = (const float*)d_in[16];
    const float* ln1_g      = (const float*)d_in[17];
    const float* ln1_b      = (const float*)d_in[18];
    const float* ff_w1      = (const float*)d_in[19];
    const float* ff_b1      = (const float*)d_in[20];
    const float* ff_w2      = (const float*)d_in[21];
    const float* ff_b2      = (const float*)d_in[22];
    const float* ln2_g      = (const float*)d_in[23];
    const float* ln2_b      = (const float*)d_in[24];
    const float* memories   = (const float*)d_in[25];
    const float* mem_agg_w  = (const float*)d_in[26];
    const float* mem_agg_b  = (const float*)d_in[27];
    const float* ggate      = (const float*)d_in[28];

    float *H, *F, *TOK, *TN, *XIN, *QKV, *AO, *S1, *X1, *FFH, *S2, *EO, *RC, *EOUT;
    cudaGetSymbolAddress((void**)&H,    g_H);
    cudaGetSymbolAddress((void**)&F,    g_F);
    cudaGetSymbolAddress((void**)&TOK,  g_TOK);
    cudaGetSymbolAddress((void**)&TN,   g_TN);
    cudaGetSymbolAddress((void**)&XIN,  g_XIN);
    cudaGetSymbolAddress((void**)&QKV,  g_QKV);
    cudaGetSymbolAddress((void**)&AO,   g_AO);
    cudaGetSymbolAddress((void**)&S1,   g_S1);
    cudaGetSymbolAddress((void**)&X1,   g_X1);
    cudaGetSymbolAddress((void**)&FFH,  g_FFH);
    cudaGetSymbolAddress((void**)&S2,   g_S2);
    cudaGetSymbolAddress((void**)&EO,   g_EO);
    cudaGetSymbolAddress((void**)&RC,   g_RC);
    cudaGetSymbolAddress((void**)&EOUT, g_EOUT);

    // ---- aligner: two big GEMMs + double LN ----
    sgemm128<<<dim3(HIDN / 128, NTOK / 128, EE), 256>>>(
        x, al_w1, al_b1, H, HIDN, DIN, 1,
        (long)NTOK * DIN, (long)DIN * HIDN, HIDN, (long)NTOK * HIDN);
    sgemm128<<<dim3(DD / 128, NTOK / 128, EE), 256>>>(
        H, al_w2, al_b2, F, DD, HIDN, 0,
        (long)NTOK * HIDN, (long)HIDN * DD, DD, (long)NTOK * DD);
    aligner_ln<<<EE * NTOK, 128>>>(al_g, al_bt);

    // ---- LSTCWA ----
    qu_kernel<<<EE * LL, 256>>>(z, wq, wk);
    seg_attn<<<EE * LL, 128>>>();
    zo_tok<<<EE * LL, 256>>>(wv, wo, bo);

    // ---- cross-context ----
    ln_rows<<<EE * LL, 128>>>(TOK, TN, nullptr, nullptr);
    cross_ctx<<<EE * LL, 128>>>();

    // ---- per-expert transformer layer ----
    sgemm64<<<dim3(3 * DD / 64, 1, EE), 256>>>(
        XIN, attn_in_w, attn_in_b, nullptr, QKV, 3 * DD, DD, 0,
        (long)LL * DD, (long)DD * 3 * DD, 3 * DD, 0, (long)LL * 3 * DD);
    mha<<<EE * HH, 64>>>();
    sgemm64<<<dim3(DD / 64, 1, EE), 256>>>(
        AO, attn_out_w, attn_out_b, XIN, S1, DD, DD, 0,
        (long)LL * DD, (long)DD * DD, DD, (long)LL * DD, (long)LL * DD);
    ln_rows<<<EE * LL, 128>>>(S1, X1, ln1_g, ln1_b);
    sgemm64<<<dim3(FFN / 64, 1, EE), 256>>>(
        X1, ff_w1, ff_b1, nullptr, FFH, FFN, DD, 1,
        (long)LL * DD, (long)DD * FFN, FFN, 0, (long)LL * FFN);
    sgemm64<<<dim3(DD / 64, 1, EE), 256>>>(
        FFH, ff_w2, ff_b2, X1, S2, DD, FFN, 0,
        (long)LL * FFN, (long)FFN * DD, DD, (long)LL * DD, (long)LL * DD);
    ln_rows<<<EE * LL, 128>>>(S2, EO, ln2_g, ln2_b);

    // ---- hierarchical memory ----
    mem_retr<<<EE * LL, 128>>>(memories);
    sgemm64<<<dim3(DD / 64, 1, EE), 256>>>(
        RC, mem_agg_w, mem_agg_b, EO, EOUT, DD, MMEM * DD, 0,
        (long)LL * MMEM * DD, 0, 0, (long)LL * DD, (long)LL * DD);

    // ---- gating + fusion ----
    fuse<<<1, 512>>>(ggate, (float*)d_out, (out_size >= LL * DD + EE) ? 1 : 0);
}

// round 3
// speedup vs baseline: 1.0703x; 1.0703x over previous
#include <cuda_runtime.h>
#include <math.h>

// ---------------- problem constants ----------------
#define EE    4
#define NTOK  8192
#define DIN   1024
#define DD    512
#define LL    64
#define SS    128          // NTOK / LL
#define MMEM  2
#define KMEM  32
#define HH    8
#define DHH   64
#define FFN   2048
#define HIDN  1024
#define SD    22.62741699796952f   // sqrt(512)

// ---------------- scratch (device globals; allocation-free) ----------------
__device__ float g_H  [EE * NTOK * HIDN];
__device__ float g_F  [EE * NTOK * DD];
__device__ float g_Q  [EE * LL * DD];
__device__ float g_U  [EE * LL * DD];
__device__ float g_CS [EE * LL * DD];
__device__ float g_ZO [EE * LL * DD];
__device__ float g_TOK[EE * LL * DD];
__device__ float g_TN [EE * LL * DD];
__device__ float g_XIN[EE * LL * DD];
__device__ float g_QKV[EE * LL * 3 * DD];
__device__ float g_AO [EE * LL * DD];
__device__ float g_S1 [EE * LL * DD];
__device__ float g_X1 [EE * LL * DD];
__device__ float g_FFH[EE * LL * FFN];
__device__ float g_S2 [EE * LL * DD];
__device__ float g_EO [EE * LL * DD];
__device__ float g_RC [EE * LL * MMEM * DD];
__device__ float g_EOUT[EE * LL * DD];

// ---------------- reduction helpers ----------------
__device__ __forceinline__ float warpSum(float v) {
#pragma unroll
    for (int o = 16; o; o >>= 1) v += __shfl_xor_sync(0xffffffffu, v, o);
    return v;
}
__device__ __forceinline__ float warpMax(float v) {
#pragma unroll
    for (int o = 16; o; o >>= 1) v = fmaxf(v, __shfl_xor_sync(0xffffffffu, v, o));
    return v;
}
__device__ __forceinline__ float blockSum(float v, float* sw, int tid, int nw) {
    int lane = tid & 31, w = tid >> 5;
    v = warpSum(v);
    if (lane == 0) sw[w] = v;
    __syncthreads();
    float t = 0.f;
    for (int i = 0; i < nw; i++) t += sw[i];
    __syncthreads();
    return t;
}
__device__ __forceinline__ float blockMax(float v, float* sw, int tid, int nw) {
    int lane = tid & 31, w = tid >> 5;
    v = warpMax(v);
    if (lane == 0) sw[w] = v;
    __syncthreads();
    float t = -1e30f;
    for (int i = 0; i < nw; i++) t = fmaxf(t, sw[i]);
    __syncthreads();
    return t;
}
__device__ __forceinline__ float clip5(float x) { return fminf(fmaxf(x, -5.f), 5.f); }

// ---------------- big SGEMM: 128x128 tile, BK=16, double-buffered ----------------
__global__ __launch_bounds__(256, 2)
void sgemm128(const float* __restrict__ A, const float* __restrict__ B,
              const float* __restrict__ bias, float* __restrict__ C,
              int Ncols, int Kdim, int relu,
              long aStr, long bStr, long biasStr, long cStr)
{
    const int e = blockIdx.z;
    A    += (long)e * aStr;
    B    += (long)e * bStr;
    bias += (long)e * biasStr;
    C    += (long)e * cStr;
    const int bx = blockIdx.x, by = blockIdx.y;

    __shared__ float As[2][16][128];
    __shared__ float Bs[2][16][128];

    const int tid = threadIdx.x;
    const int tx = tid & 15, ty = tid >> 4;

    float acc[8][8] = {};

    const int a_r = tid >> 2,  a_c = (tid & 3) << 2;    // A tile 128x16
    const int b_r = tid >> 5,  b_c = (tid & 31) << 2;   // B tile 16x128

    const float* Ab = A + (long)(by * 128 + a_r) * Kdim + a_c;
    const float* Bb = B + (long)b_r * Ncols + bx * 128 + b_c;

    const int NT = Kdim >> 4;

    float4 pa0 = *(const float4*)(Ab);
    float4 pa1 = *(const float4*)(Ab + 64l * Kdim);
    float4 pb0 = *(const float4*)(Bb);
    float4 pb1 = *(const float4*)(Bb + 8l * Ncols);

    // store stage 0
    As[0][a_c + 0][a_r] = pa0.x; As[0][a_c + 1][a_r] = pa0.y;
    As[0][a_c + 2][a_r] = pa0.z; As[0][a_c + 3][a_r] = pa0.w;
    As[0][a_c + 0][a_r + 64] = pa1.x; As[0][a_c + 1][a_r + 64] = pa1.y;
    As[0][a_c + 2][a_r + 64] = pa1.z; As[0][a_c + 3][a_r + 64] = pa1.w;
    *(float4*)&Bs[0][b_r][b_c]     = pb0;
    *(float4*)&Bs[0][b_r + 8][b_c] = pb1;

    for (int it = 0; it < NT; it++) {
        __syncthreads();
        const int cur = it & 1;
        if (it + 1 < NT) {
            const long kt = (long)(it + 1) << 4;
            pa0 = *(const float4*)(Ab + kt);
            pa1 = *(const float4*)(Ab + 64l * Kdim + kt);
            pb0 = *(const float4*)(Bb + kt * Ncols);
            pb1 = *(const float4*)(Bb + (kt + 8) * Ncols);
        }
#pragma unroll
        for (int kk = 0; kk < 16; kk++) {
            float4 a0 = *(const float4*)&As[cur][kk][ty * 4];
            float4 a1 = *(const float4*)&As[cur][kk][ty * 4 + 64];
            float4 b0 = *(const float4*)&Bs[cur][kk][tx * 4];
            float4 b1 = *(const float4*)&Bs[cur][kk][tx * 4 + 64];
            float ar[8] = {a0.x, a0.y, a0.z, a0.w, a1.x, a1.y, a1.z, a1.w};
            float br[8] = {b0.x, b0.y, b0.z, b0.w, b1.x, b1.y, b1.z, b1.w};
#pragma unroll
            for (int i = 0; i < 8; i++)
#pragma unroll
                for (int j = 0; j < 8; j++)
                    acc[i][j] += ar[i] * br[j];
        }
        if (it + 1 < NT) {
            const int nxt = cur ^ 1;
            As[nxt][a_c + 0][a_r] = pa0.x; As[nxt][a_c + 1][a_r] = pa0.y;
            As[nxt][a_c + 2][a_r] = pa0.z; As[nxt][a_c + 3][a_r] = pa0.w;
            As[nxt][a_c + 0][a_r + 64] = pa1.x; As[nxt][a_c + 1][a_r + 64] = pa1.y;
            As[nxt][a_c + 2][a_r + 64] = pa1.z; As[nxt][a_c + 3][a_r + 64] = pa1.w;
            *(float4*)&Bs[nxt][b_r][b_c]     = pb0;
            *(float4*)&Bs[nxt][b_r + 8][b_c] = pb1;
        }
    }

#pragma unroll
    for (int i = 0; i < 8; i++) {
        int row = by * 128 + ty * 4 + ((i < 4) ? i : 60 + i);
#pragma unroll
        for (int jh = 0; jh < 2; jh++) {
            int col = bx * 128 + tx * 4 + jh * 64;
            float4 v;
            v.x = acc[i][jh * 4 + 0] + bias[col + 0];
            v.y = acc[i][jh * 4 + 1] + bias[col + 1];
            v.z = acc[i][jh * 4 + 2] + bias[col + 2];
            v.w = acc[i][jh * 4 + 3] + bias[col + 3];
            if (relu) {
                v.x = fmaxf(v.x, 0.f); v.y = fmaxf(v.y, 0.f);
                v.z = fmaxf(v.z, 0.f); v.w = fmaxf(v.w, 0.f);
            }
            *(float4*)(C + (long)row * Ncols + col) = v;
        }
    }
}

// ---------------- small SGEMM: 64 rows, 64-col tiles, BK=16, 4x4/thread ----------------
// transB: B is [N, K] row-major (u = q @ B^T)
__global__ __launch_bounds__(256)
void sgemm64(const float* __restrict__ A, const float* __restrict__ B,
             const float* __restrict__ bias, const float* __restrict__ addend,
             float* __restrict__ C,
             int Ncols, int Kdim, int relu, int transB,
             long aStr, long bStr, long biasStr, long addStr, long cStr)
{
    const int e = blockIdx.z;
    A += (long)e * aStr;
    B += (long)e * bStr;
    C += (long)e * cStr;
    const float* biasE = bias ? bias + (long)e * biasStr : nullptr;
    const float* addE  = addend ? addend + (long)e * addStr : nullptr;
    const int bx = blockIdx.x;

    __shared__ float As[16][64];
    __shared__ float Bs[16][64];

    const int tid = threadIdx.x;
    const int tx = tid & 15, ty = tid >> 4;

    float acc[4][4] = {};

    const int a_r = tid >> 2,  a_c = (tid & 3) << 2;   // 64x16
    const int b_r = tid >> 4,  b_c = (tid & 15) << 2;  // 16x64 (normal)
    const int tb_n = tid & 63, tb_k = (tid >> 6) << 2; // transB: 64n x 16k

    const float* Ab = A + (long)a_r * Kdim + a_c;

    for (int kt = 0; kt < Kdim; kt += 16) {
        float4 va = *(const float4*)(Ab + kt);
        As[a_c + 0][a_r] = va.x; As[a_c + 1][a_r] = va.y;
        As[a_c + 2][a_r] = va.z; As[a_c + 3][a_r] = va.w;
        if (!transB) {
            float4 vb = *(const float4*)(B + (long)(b_r + kt) * Ncols + bx * 64 + b_c);
            *(float4*)&Bs[b_r][b_c] = vb;
        } else {
            float4 vb = *(const float4*)(B + (long)(bx * 64 + tb_n) * Kdim + kt + tb_k);
            Bs[tb_k + 0][tb_n] = vb.x; Bs[tb_k + 1][tb_n] = vb.y;
            Bs[tb_k + 2][tb_n] = vb.z; Bs[tb_k + 3][tb_n] = vb.w;
        }
        __syncthreads();
#pragma unroll
        for (int kk = 0; kk < 16; kk++) {
            float4 a = *(const float4*)&As[kk][ty * 4];
            float4 b = *(const float4*)&Bs[kk][tx * 4];
            float ar[4] = {a.x, a.y, a.z, a.w};
            float br[4] = {b.x, b.y, b.z, b.w};
#pragma unroll
            for (int i = 0; i < 4; i++)
#pragma unroll
                for (int j = 0; j < 4; j++)
                    acc[i][j] += ar[i] * br[j];
        }
        __syncthreads();
    }

#pragma unroll
    for (int i = 0; i < 4; i++) {
        int row = ty * 4 + i;
        int col = bx * 64 + tx * 4;
        float4 v;
        v.x = acc[i][0]; v.y = acc[i][1]; v.z = acc[i][2]; v.w = acc[i][3];
        if (biasE) {
            v.x += biasE[col + 0]; v.y += biasE[col + 1];
            v.z += biasE[col + 2]; v.w += biasE[col + 3];
        }
        if (addE) {
            float4 a = *(const float4*)(addE + (long)row * Ncols + col);
            v.x += a.x; v.y += a.y; v.z += a.z; v.w += a.w;
        }
        if (relu) {
            v.x = fmaxf(v.x, 0.f); v.y = fmaxf(v.y, 0.f);
            v.z = fmaxf(v.z, 0.f); v.w = fmaxf(v.w, 0.f);
        }
        *(float4*)(C + (long)row * Ncols + col) = v;
    }
}

// ---------------- aligner double-LN (in place on g_F): f = LN(LN(y)*g + bt) ----------------
__global__ __launch_bounds__(128)
void aligner_ln(const float* __restrict__ g, const float* __restrict__ bt)
{
    __shared__ float sw[4];
    const int row = blockIdx.x;          // E*NTOK rows
    const int e = row >> 13;             // / 8192
    const int tid = threadIdx.x;
    float* rp = g_F + (long)row * DD;

    float v[4]; float s = 0.f, q = 0.f;
#pragma unroll
    for (int i = 0; i < 4; i++) {
        v[i] = rp[tid + i * 128];
        s += v[i]; q += v[i] * v[i];
    }
    s = blockSum(s, sw, tid, 4);
    q = blockSum(q, sw, tid, 4);
    float mu = s * (1.f / DD);
    float rstd = rsqrtf(q * (1.f / DD) - mu * mu + 1e-5f);

    float s2 = 0.f, q2 = 0.f;
#pragma unroll
    for (int i = 0; i < 4; i++) {
        int d = tid + i * 128;
        v[i] = (v[i] - mu) * rstd * g[e * DD + d] + bt[e * DD + d];
        s2 += v[i]; q2 += v[i] * v[i];
    }
    s2 = blockSum(s2, sw, tid, 4);
    q2 = blockSum(q2, sw, tid, 4);
    mu = s2 * (1.f / DD);
    rstd = rsqrtf(q2 * (1.f / DD) - mu * mu + 1e-5f);
#pragma unroll
    for (int i = 0; i < 4; i++)
        rp[tid + i * 128] = (v[i] - mu) * rstd;
}

// ---------------- generic row LN (rows = E*LL) ----------------
__global__ __launch_bounds__(128)
void ln_rows(const float* __restrict__ in, float* __restrict__ out,
             const float* __restrict__ gamma, const float* __restrict__ beta)
{
    __shared__ float sw[4];
    const int row = blockIdx.x;
    const int e = row >> 6;
    const int tid = threadIdx.x;
    const float* rp = in + (long)row * DD;

    float v[4]; float s = 0.f, q = 0.f;
#pragma unroll
    for (int i = 0; i < 4; i++) {
        v[i] = rp[tid + i * 128];
        s += v[i]; q += v[i] * v[i];
    }
    s = blockSum(s, sw, tid, 4);
    q = blockSum(q, sw, tid, 4);
    float mu = s * (1.f / DD);
    float rstd = rsqrtf(q * (1.f / DD) - mu * mu + 1e-5f);
#pragma unroll
    for (int i = 0; i < 4; i++) {
        int d = tid + i * 128;
        float o = (v[i] - mu) * rstd;
        if (gamma) o = o * gamma[e * DD + d] + beta[e * DD + d];
        out[(long)row * DD + d] = o;
    }
}

// ---------------- LSTCWA stage 2: seg softmax + weighted segment sum ----------------
__global__ __launch_bounds__(128)
void seg_attn()
{
    const int row = blockIdx.x;   // e*64 + l
    const int e = row >> 6, l = row & 63;
    const int tid = threadIdx.x;
    const int lane = tid & 31, w = tid >> 5;
    __shared__ float u[DD];
    __shared__ float sc[SS];
    __shared__ float sw[4];

#pragma unroll
    for (int i = 0; i < 4; i++) u[tid + i * 128] = g_U[(long)row * DD + tid + i * 128];
    __syncthreads();

    const float* F = g_F + ((long)e * NTOK + (long)l * SS) * DD;
    for (int s = w; s < SS; s += 4) {
        const float* fr = F + (long)s * DD;
        float p = 0.f;
        for (int t = lane; t < DD; t += 32) p += fr[t] * u[t];
        p = warpSum(p);
        if (lane == 0) sc[s] = clip5(p * (1.f / SD));
    }
    __syncthreads();

    float x = sc[tid];
    float mx = blockMax(x, sw, tid, 4);
    float ex = expf(x - mx);
    float sum = blockSum(ex, sw, tid, 4);
    sc[tid] = ex / sum;
    __syncthreads();

    for (int d = tid; d < DD; d += 128) {
        float a = 0.f;
        for (int s = 0; s < SS; s++) a += sc[s] * F[(long)s * DD + d];
        g_CS[(long)row * DD + d] = a;
    }
}

// ---------------- cross-backbone context attention ----------------
__global__ __launch_bounds__(128)
void cross_ctx()
{
    const int row = blockIdx.x;
    const int e = row >> 6;
    const int ec = (e == 0) ? 1 : 0;
    const int tid = threadIdx.x;
    const int lane = tid & 31, w = tid >> 5;
    __shared__ float tr[DD];
    __shared__ float sc[LL];
    __shared__ float sw[4];

#pragma unroll
    for (int i = 0; i < 4; i++) tr[tid + i * 128] = g_TN[(long)row * DD + tid + i * 128];
    __syncthreads();

    const float* C = g_TN + (long)ec * LL * DD;
    for (int m = w; m < LL; m += 4) {
        const float* cr = C + (long)m * DD;
        float p = 0.f;
        for (int t = lane; t < DD; t += 32) p += tr[t] * cr[t];
        p = warpSum(p);
        if (lane == 0) sc[m] = clip5(p * (1.f / SD));
    }
    __syncthreads();

    float x = (tid < LL) ? sc[tid] : -1e30f;
    float mx = blockMax(x, sw, tid, 4);
    float ex = (tid < LL) ? expf(x - mx) : 0.f;
    float sum = blockSum(ex, sw, tid, 4);
    if (tid < LL) sc[tid] = ex / sum;
    __syncthreads();

    for (int d = tid; d < DD; d += 128) {
        float a = tr[d];
        for (int m = 0; m < LL; m++) a += sc[m] * C[(long)m * DD + d];
        g_XIN[(long)row * DD + d] = a;
    }
}

// ---------------- MHA (per expert, per head); scores kept in registers ----------------
__global__ __launch_bounds__(64)
void mha()
{
    const int e = blockIdx.x >> 3;
    const int h = blockIdx.x & 7;
    const int tid = threadIdx.x;     // = query index l
    __shared__ float ks[64 * 64];
    __shared__ float vs[64 * 64];

    const float* Q = g_QKV + (long)e * LL * 1536;
    for (int idx = tid; idx < 4096; idx += 64) {
        int m = idx >> 6, d = idx & 63;
        ks[idx] = Q[(long)m * 1536 + 512 + h * 64 + d];
        vs[idx] = Q[(long)m * 1536 + 1024 + h * 64 + d];
    }
    float qv[64];
#pragma unroll
    for (int i = 0; i < 64; i++) qv[i] = Q[(long)tid * 1536 + h * 64 + i];
    __syncthreads();

    float srow[64];
    float mx = -1e30f;
#pragma unroll
    for (int m = 0; m < 64; m++) {
        float s = 0.f;
#pragma unroll
        for (int i = 0; i < 64; i++) s += qv[i] * ks[m * 64 + i];
        s *= 0.125f;
        srow[m] = s;
        mx = fmaxf(mx, s);
    }
    float sum = 0.f;
#pragma unroll
    for (int m = 0; m < 64; m++) {
        float p = expf(srow[m] - mx);
        srow[m] = p;
        sum += p;
    }
    float inv = 1.f / sum;
#pragma unroll
    for (int m = 0; m < 64; m++) srow[m] *= inv;

    for (int d = 0; d < 64; d++) {
        float a = 0.f;
#pragma unroll
        for (int m = 0; m < 64; m++) a += srow[m] * vs[m * 64 + d];
        g_AO[((long)e * LL + tid) * DD + h * 64 + d] = a;
    }
}

// ---------------- hierarchical memory retrieval ----------------
__global__ __launch_bounds__(128)
void mem_retr(const float* __restrict__ mem)
{
    const int row = blockIdx.x;
    const int tid = threadIdx.x;
    const int lane = tid & 31, w = tid >> 5;
    __shared__ float er[DD];
    __shared__ float sa[MMEM * KMEM];

#pragma unroll
    for (int i = 0; i < 4; i++) er[tid + i * 128] = g_EO[(long)row * DD + tid + i * 128];
    __syncthreads();

    for (int p = w; p < MMEM * KMEM; p += 4) {
        const float* mr = mem + (long)p * DD;
        float s = 0.f;
        for (int t = lane; t < DD; t += 32) s += er[t] * mr[t];
        s = warpSum(s);
        if (lane == 0) sa[p] = clip5(s * (1.f / SD));
    }
    __syncthreads();

    if (tid < MMEM) {
        float mx = -1e30f;
        for (int k = 0; k < KMEM; k++) mx = fmaxf(mx, sa[tid * KMEM + k]);
        float sum = 0.f;
        for (int k = 0; k < KMEM; k++) {
            float pz = expf(sa[tid * KMEM + k] - mx);
            sa[tid * KMEM + k] = pz;
            sum += pz;
        }
        float inv = 1.f / sum;
        for (int k = 0; k < KMEM; k++) sa[tid * KMEM + k] *= inv;
    }
    __syncthreads();

    for (int d = tid; d < DD; d += 128) {
        float r0 = 0.f, r1 = 0.f;
        for (int k = 0; k < KMEM; k++) {
            r0 += sa[k] * mem[(long)k * DD + d];
            r1 += sa[KMEM + k] * mem[(long)(KMEM + k) * DD + d];
        }
        g_RC[(long)row * (MMEM * DD) + d] = r0;
        g_RC[(long)row * (MMEM * DD) + DD + d] = r1;
    }
}

// ---------------- global gating + fusion ----------------
__global__ __launch_bounds__(512)
void fuse(const float* __restrict__ gate, float* __restrict__ out, int write_gw)
{
    __shared__ float sw[16];
    __shared__ float logit[EE];
    __shared__ float gws[EE];
    const int tid = threadIdx.x;

    for (int e = 0; e < EE; e++) {
        float p = 0.f;
        for (int idx = tid; idx < LL * DD; idx += 512)
            p += g_EOUT[(long)e * LL * DD + idx] * gate[idx & (DD - 1)];
        p = blockSum(p, sw, tid, 16);
        if (tid == 0) logit[e] = p * (1.f / LL);
        __syncthreads();
    }
    if (tid == 0) {
        float mx = -1e30f;
        float c[EE];
        for (int e = 0; e < EE; e++) { c[e] = clip5(logit[e]); mx = fmaxf(mx, c[e]); }
        float sum = 0.f;
        for (int e = 0; e < EE; e++) { c[e] = expf(c[e] - mx); sum += c[e]; }
        for (int e = 0; e < EE; e++) {
            gws[e] = c[e] / sum;
            if (write_gw) out[LL * DD + e] = gws[e];
        }
    }
    __syncthreads();
    for (int idx = tid; idx < LL * DD; idx += 512) {
        float a = 0.f;
        for (int e = 0; e < EE; e++) a += gws[e] * g_EOUT[(long)e * LL * DD + idx];
        out[idx] = a;
    }
}

// ---------------- host launcher ----------------
extern "C" void kernel_launch(void* const* d_in, const int* in_sizes, int n_in,
                              void* d_out, int out_size)
{
    (void)in_sizes; (void)n_in;
    const float* x          = (const float*)d_in[0];
    const float* al_w1      = (const float*)d_in[1];
    const float* al_b1      = (const float*)d_in[2];
    const float* al_w2      = (const float*)d_in[3];
    const float* al_b2      = (const float*)d_in[4];
    const float* al_g       = (const float*)d_in[5];
    const float* al_bt      = (const float*)d_in[6];
    const float* z          = (const float*)d_in[7];
    const float* wq         = (const float*)d_in[8];
    const float* wk         = (const float*)d_in[9];
    const float* wv         = (const float*)d_in[10];
    const float* wo         = (const float*)d_in[11];
    const float* bo         = (const float*)d_in[12];
    const float* attn_in_w  = (const float*)d_in[13];
    const float* attn_in_b  = (const float*)d_in[14];
    const float* attn_out_w = (const float*)d_in[15];
    const float* attn_out_b = (const float*)d_in[16];
    const float* ln1_g      = (const float*)d_in[17];
    const float* ln1_b      = (const float*)d_in[18];
    const float* ff_w1      = (const float*)d_in[19];
    const float* ff_b1      = (const float*)d_in[20];
    const float* ff_w2      = (const float*)d_in[21];
    const float* ff_b2      = (const float*)d_in[22];
    const float* ln2_g      = (const float*)d_in[23];
    const float* ln2_b      = (const float*)d_in[24];
    const float* memories   = (const float*)d_in[25];
    const float* mem_agg_w  = (const float*)d_in[26];
    const float* mem_agg_b  = (const float*)d_in[27];
    const float* ggate      = (const float*)d_in[28];

    float *H, *F, *Q, *U, *CS, *ZO, *TOK, *TN, *XIN, *QKV, *AO, *S1, *X1, *FFH, *S2, *EO, *RC, *EOUT;
    cudaGetSymbolAddress((void**)&H,    g_H);
    cudaGetSymbolAddress((void**)&F,    g_F);
    cudaGetSymbolAddress((void**)&Q,    g_Q);
    cudaGetSymbolAddress((void**)&U,    g_U);
    cudaGetSymbolAddress((void**)&CS,   g_CS);
    cudaGetSymbolAddress((void**)&ZO,   g_ZO);
    cudaGetSymbolAddress((void**)&TOK,  g_TOK);
    cudaGetSymbolAddress((void**)&TN,   g_TN);
    cudaGetSymbolAddress((void**)&XIN,  g_XIN);
    cudaGetSymbolAddress((void**)&QKV,  g_QKV);
    cudaGetSymbolAddress((void**)&AO,   g_AO);
    cudaGetSymbolAddress((void**)&S1,   g_S1);
    cudaGetSymbolAddress((void**)&X1,   g_X1);
    cudaGetSymbolAddress((void**)&FFH,  g_FFH);
    cudaGetSymbolAddress((void**)&S2,   g_S2);
    cudaGetSymbolAddress((void**)&EO,   g_EO);
    cudaGetSymbolAddress((void**)&RC,   g_RC);
    cudaGetSymbolAddress((void**)&EOUT, g_EOUT);

    const long LD = (long)LL * DD;

    // ---- aligner: two big GEMMs + double LN ----
    sgemm128<<<dim3(HIDN / 128, NTOK / 128, EE), 256>>>(
        x, al_w1, al_b1, H, HIDN, DIN, 1,
        (long)NTOK * DIN, (long)DIN * HIDN, HIDN, (long)NTOK * HIDN);
    sgemm128<<<dim3(DD / 128, NTOK / 128, EE), 256>>>(
        H, al_w2, al_b2, F, DD, HIDN, 0,
        (long)NTOK * HIDN, (long)HIDN * DD, DD, (long)NTOK * DD);
    aligner_ln<<<EE * NTOK, 128>>>(al_g, al_bt);

    // ---- LSTCWA:  q = z@wq ;  u = q@wk^T ;  seg attn ;  zo = cs@wv ;  tok = zo@wo + bo ----
    sgemm64<<<dim3(DD / 64, 1, EE), 256>>>(
        z, wq, nullptr, nullptr, Q, DD, DD, 0, 0,
        LD, (long)DD * DD, 0, 0, LD);
    sgemm64<<<dim3(DD / 64, 1, EE), 256>>>(
        Q, wk, nullptr, nullptr, U, DD, DD, 0, 1,
        LD, (long)DD * DD, 0, 0, LD);
    seg_attn<<<EE * LL, 128>>>();
    sgemm64<<<dim3(DD / 64, 1, EE), 256>>>(
        CS, wv, nullptr, nullptr, ZO, DD, DD, 0, 0,
        LD, (long)DD * DD, 0, 0, LD);
    sgemm64<<<dim3(DD / 64, 1, EE), 256>>>(
        ZO, wo, bo, nullptr, TOK, DD, DD, 0, 0,
        LD, (long)DD * DD, DD, 0, LD);

    // ---- cross-context ----
    ln_rows<<<EE * LL, 128>>>(TOK, TN, nullptr, nullptr);
    cross_ctx<<<EE * LL, 128>>>();

    // ---- per-expert transformer layer ----
    sgemm64<<<dim3(3 * DD / 64, 1, EE), 256>>>(
        XIN, attn_in_w, attn_in_b, nullptr, QKV, 3 * DD, DD, 0, 0,
        LD, (long)DD * 3 * DD, 3 * DD, 0, (long)LL * 3 * DD);
    mha<<<EE * HH, 64>>>();
    sgemm64<<<dim3(DD / 64, 1, EE), 256>>>(
        AO, attn_out_w, attn_out_b, XIN, S1, DD, DD, 0, 0,
        LD, (long)DD * DD, DD, LD, LD);
    ln_rows<<<EE * LL, 128>>>(S1, X1, ln1_g, ln1_b);
    sgemm64<<<dim3(FFN / 64, 1, EE), 256>>>(
        X1, ff_w1, ff_b1, nullptr, FFH, FFN, DD, 1, 0,
        LD, (long)DD * FFN, FFN, 0, (long)LL * FFN);
    sgemm64<<<dim3(DD / 64, 1, EE), 256>>>(
        FFH, ff_w2, ff_b2, X1, S2, DD, FFN, 0, 0,
        (long)LL * FFN, (long)FFN * DD, DD, LD, LD);
    ln_rows<<<EE * LL, 128>>>(S2, EO, ln2_g, ln2_b);

    // ---- hierarchical memory ----
    mem_retr<<<EE * LL, 128>>>(memories);
    sgemm64<<<dim3(DD / 64, 1, EE), 256>>>(
        RC, mem_agg_w, mem_agg_b, EO, EOUT, DD, MMEM * DD, 0, 0,
        (long)LL * MMEM * DD, 0, 0, LD, LD);

    // ---- gating + fusion ----
    fuse<<<1, 512>>>(ggate, (float*)d_out, (out_size >= LL * DD + EE) ? 1 : 0);
}